// round 2
// baseline (speedup 1.0000x reference)
#include <cuda_runtime.h>
#include <cuda_pipeline.h>

#define NN    8192
#define DD    64
#define HH    4096
#define SS    4          // samples per block
#define TPS   128        // threads per sample
#define CH    32         // hidden units per thread (HH/TPS)
#define BLOCK 512        // SS*TPS

// Accurate-enough fast tanh: EX2 + RCP (2 MUFU), rel err ~1e-7.
// Robust at extremes: x->+inf: e=inf -> 1-0 = 1; x->-inf: e=0 -> 1-2 = -1.
static __device__ __forceinline__ float ftanh(float x) {
    float e = __expf(2.0f * x);
    return 1.0f - __fdividef(2.0f, e + 1.0f);
}

__global__ void __launch_bounds__(BLOCK, 1)
qnade_kernel(const float* __restrict__ gx,  const float* __restrict__ gW1,
             const float* __restrict__ gb1, const float* __restrict__ gW2,
             const float* __restrict__ gb2, float* __restrict__ gout)
{
    __shared__ float  sW1[2][HH];                 // double-buffered W1 row
    __shared__ float  sX[SS][DD];                 // spin rows for this block
    __shared__ float2 sPart[2][SS][TPS / 32];     // per-warp reduction partials

    const int tid  = threadIdx.x;
    const int s    = tid >> 7;       // sample within block
    const int wg   = tid & 127;      // thread within sample group
    const int wis  = wg >> 5;        // warp within sample group
    const int lane = tid & 31;
    const int n    = blockIdx.x * SS + s;
    const int base = wg * CH;

    // stage spins
    for (int i = tid; i < SS * DD; i += BLOCK)
        sX[i >> 6][i & 63] = gx[(blockIdx.x * SS + (i >> 6)) * DD + (i & 63)];

    // prefetch W1 row 0 into buffer 0
    {
        const float4* src = (const float4*)gW1;
        float4*       dst = (float4*)sW1[0];
        for (int i = tid; i < HH / 4; i += BLOCK)
            __pipeline_memcpy_async(dst + i, src + i, 16);
        __pipeline_commit();
    }

    // per-thread persistent state: h accumulator (starts at b1), W2 columns
    float h[CH], w20[CH], w21[CH];
    {
        const float4* b1v = (const float4*)(gb1 + base);
        const float4* w2v = (const float4*)(gW2 + 2 * base);  // [H,2] row-major
#pragma unroll
        for (int k4 = 0; k4 < CH / 4; k4++) {
            float4 b = b1v[k4];
            h[k4 * 4 + 0] = b.x; h[k4 * 4 + 1] = b.y;
            h[k4 * 4 + 2] = b.z; h[k4 * 4 + 3] = b.w;
        }
#pragma unroll
        for (int k2 = 0; k2 < CH / 2; k2++) {
            float4 w = w2v[k2];
            w20[k2 * 2 + 0] = w.x; w21[k2 * 2 + 0] = w.y;
            w20[k2 * 2 + 1] = w.z; w21[k2 * 2 + 1] = w.w;
        }
    }
    const float b20 = gb2[0], b21 = gb2[1];
    float wav = 1.0f;

    __pipeline_wait_prior(0);
    __syncthreads();

    for (int d = 0; d < DD; d++) {
        const int p = d & 1;

        // prefetch next W1 row into the other buffer (async, overlapped)
        if (d + 1 < DD) {
            const float4* src = (const float4*)(gW1 + (size_t)(d + 1) * HH);
            float4*       dst = (float4*)sW1[1 - p];
            for (int i = tid; i < HH / 4; i += BLOCK)
                __pipeline_memcpy_async(dst + i, src + i, 16);
            __pipeline_commit();
        }

        const float xd = sX[s][d];
        float a0 = 0.f, a1 = 0.f;
        const float4* w1v = (const float4*)(sW1[p] + base);

        // fused: tanh(current h) -> dot with W2 cols; then rank-1 update of h
#pragma unroll
        for (int k4 = 0; k4 < CH / 4; k4++) {
            float4 w = w1v[k4];
            float t0 = ftanh(h[k4 * 4 + 0]);
            float t1 = ftanh(h[k4 * 4 + 1]);
            float t2 = ftanh(h[k4 * 4 + 2]);
            float t3 = ftanh(h[k4 * 4 + 3]);
            h[k4 * 4 + 0] = fmaf(xd, w.x, h[k4 * 4 + 0]);
            h[k4 * 4 + 1] = fmaf(xd, w.y, h[k4 * 4 + 1]);
            h[k4 * 4 + 2] = fmaf(xd, w.z, h[k4 * 4 + 2]);
            h[k4 * 4 + 3] = fmaf(xd, w.w, h[k4 * 4 + 3]);
            a0 = fmaf(t0, w20[k4 * 4 + 0], a0); a1 = fmaf(t0, w21[k4 * 4 + 0], a1);
            a0 = fmaf(t1, w20[k4 * 4 + 1], a0); a1 = fmaf(t1, w21[k4 * 4 + 1], a1);
            a0 = fmaf(t2, w20[k4 * 4 + 2], a0); a1 = fmaf(t2, w21[k4 * 4 + 2], a1);
            a0 = fmaf(t3, w20[k4 * 4 + 3], a0); a1 = fmaf(t3, w21[k4 * 4 + 3], a1);
        }

        // warp reduction of the two dot products
#pragma unroll
        for (int off = 16; off; off >>= 1) {
            a0 += __shfl_xor_sync(0xffffffffu, a0, off);
            a1 += __shfl_xor_sync(0xffffffffu, a1, off);
        }
        if (lane == 0) sPart[p][s][wis] = make_float2(a0, a1);

        __pipeline_wait_prior(0);   // next W1 row landed
        __syncthreads();            // partials visible + buffer swap safe

        // per-sample leader finishes the 2-wide head
        if (wg == 0) {
            float z0 = b20, z1 = b21;
#pragma unroll
            for (int w = 0; w < TPS / 32; w++) {
                float2 v = sPart[p][s][w];
                z0 += v.x; z1 += v.y;
            }
            float o0 = ftanh(z0), o1 = ftanh(z1);
            float nrm = fmaxf(sqrtf(o0 * o0 + o1 * o1), 1e-12f);
            float sel = (xd > 0.f ? o0 : o1) / nrm;
            wav *= sel;
        }
    }

    if (wg == 0) gout[n] = wav;
}

extern "C" void kernel_launch(void* const* d_in, const int* in_sizes, int n_in,
                              void* d_out, int out_size) {
    const float* x  = (const float*)d_in[0];
    const float* W1 = (const float*)d_in[1];
    const float* b1 = (const float*)d_in[2];
    const float* W2 = (const float*)d_in[3];
    const float* b2 = (const float*)d_in[4];
    qnade_kernel<<<NN / SS, BLOCK>>>(x, W1, b1, W2, b2, (float*)d_out);
}

// round 3
// speedup vs baseline: 2.2260x; 2.2260x over previous
#include <cuda_runtime.h>
#include <cuda_pipeline.h>

#define NN    8192
#define DD    64
#define HH    4096
#define SS    4          // samples per block
#define TPS   128        // threads per sample
#define CH    32         // hidden units per thread (HH/TPS)
#define BLOCK 512        // SS*TPS

// Accurate fast tanh: EX2 + RCP (2 MUFU), rel err ~1e-7, robust at +/-inf.
static __device__ __forceinline__ float ftanh(float x) {
    float e = __expf(2.0f * x);
    return 1.0f - __fdividef(2.0f, e + 1.0f);
}

__global__ void __launch_bounds__(BLOCK, 1)
qnade_kernel(const float* __restrict__ gx,  const float* __restrict__ gW1,
             const float* __restrict__ gb1, const float* __restrict__ gW2,
             const float* __restrict__ gb2, float* __restrict__ gout)
{
    __shared__ float  sW1[2][HH];                 // double-buffered W1 row
    __shared__ float  sX[SS][DD];                 // spin rows for this block
    __shared__ float2 sPart[2][SS][TPS / 32];     // per-warp reduction partials

    const int tid  = threadIdx.x;
    const int s    = tid >> 7;       // sample within block
    const int wg   = tid & 127;      // thread within sample group
    const int wis  = wg >> 5;        // warp within sample group
    const int lane = tid & 31;
    const int n    = blockIdx.x * SS + s;

    // Ownership map (bank-conflict-free): thread wg owns hidden units
    //   idx(k4, j) = wg*4 + 512*k4 + j   (j = 0..3, k4 = 0..7)
    // As float4 indices: wg + 128*k4  -> lane stride 16B in SMEM -> conflict-free.

    // stage spins
    for (int i = tid; i < SS * DD; i += BLOCK)
        sX[i >> 6][i & 63] = gx[(blockIdx.x * SS + (i >> 6)) * DD + (i & 63)];

    // prefetch W1 row 0 into buffer 0
    {
        const float4* src = (const float4*)gW1;
        float4*       dst = (float4*)sW1[0];
        for (int i = tid; i < HH / 4; i += BLOCK)
            __pipeline_memcpy_async(dst + i, src + i, 16);
        __pipeline_commit();
    }

    // per-thread persistent state: h accumulator (starts at b1), W2 columns
    float h[CH], w20[CH], w21[CH];
    {
        const float4* b1v = (const float4*)gb1;
        const float4* w2v = (const float4*)gW2;   // [H,2] row-major
#pragma unroll
        for (int k4 = 0; k4 < CH / 4; k4++) {
            const int f4 = wg + 128 * k4;         // float4 index of owned quad
            float4 b = b1v[f4];
            h[k4 * 4 + 0] = b.x; h[k4 * 4 + 1] = b.y;
            h[k4 * 4 + 2] = b.z; h[k4 * 4 + 3] = b.w;
            float4 wa = w2v[2 * f4 + 0];          // hidden units 4f4+0,4f4+1
            float4 wb = w2v[2 * f4 + 1];          // hidden units 4f4+2,4f4+3
            w20[k4 * 4 + 0] = wa.x; w21[k4 * 4 + 0] = wa.y;
            w20[k4 * 4 + 1] = wa.z; w21[k4 * 4 + 1] = wa.w;
            w20[k4 * 4 + 2] = wb.x; w21[k4 * 4 + 2] = wb.y;
            w20[k4 * 4 + 3] = wb.z; w21[k4 * 4 + 3] = wb.w;
        }
    }
    const float b20 = gb2[0], b21 = gb2[1];
    float wav = 1.0f;

    __pipeline_wait_prior(0);
    __syncthreads();

    for (int d = 0; d < DD; d++) {
        const int p = d & 1;

        // prefetch next W1 row into the other buffer (async, overlapped)
        if (d + 1 < DD) {
            const float4* src = (const float4*)(gW1 + (size_t)(d + 1) * HH);
            float4*       dst = (float4*)sW1[1 - p];
            for (int i = tid; i < HH / 4; i += BLOCK)
                __pipeline_memcpy_async(dst + i, src + i, 16);
            __pipeline_commit();
        }

        const float xd = sX[s][d];
        float a0 = 0.f, a1 = 0.f;
        const float4* w1v = (const float4*)sW1[p];

        // fused: tanh(current h) -> dot with W2 cols; then rank-1 update of h
#pragma unroll
        for (int k4 = 0; k4 < CH / 4; k4++) {
            float4 w = w1v[wg + 128 * k4];        // conflict-free LDS.128
            float t0 = ftanh(h[k4 * 4 + 0]);
            float t1 = ftanh(h[k4 * 4 + 1]);
            float t2 = ftanh(h[k4 * 4 + 2]);
            float t3 = ftanh(h[k4 * 4 + 3]);
            h[k4 * 4 + 0] = fmaf(xd, w.x, h[k4 * 4 + 0]);
            h[k4 * 4 + 1] = fmaf(xd, w.y, h[k4 * 4 + 1]);
            h[k4 * 4 + 2] = fmaf(xd, w.z, h[k4 * 4 + 2]);
            h[k4 * 4 + 3] = fmaf(xd, w.w, h[k4 * 4 + 3]);
            a0 = fmaf(t0, w20[k4 * 4 + 0], a0); a1 = fmaf(t0, w21[k4 * 4 + 0], a1);
            a0 = fmaf(t1, w20[k4 * 4 + 1], a0); a1 = fmaf(t1, w21[k4 * 4 + 1], a1);
            a0 = fmaf(t2, w20[k4 * 4 + 2], a0); a1 = fmaf(t2, w21[k4 * 4 + 2], a1);
            a0 = fmaf(t3, w20[k4 * 4 + 3], a0); a1 = fmaf(t3, w21[k4 * 4 + 3], a1);
        }

        // warp reduction of the two dot products
#pragma unroll
        for (int off = 16; off; off >>= 1) {
            a0 += __shfl_xor_sync(0xffffffffu, a0, off);
            a1 += __shfl_xor_sync(0xffffffffu, a1, off);
        }
        if (lane == 0) sPart[p][s][wis] = make_float2(a0, a1);

        __pipeline_wait_prior(0);   // next W1 row landed
        __syncthreads();            // partials visible + buffer swap safe

        // per-sample leader finishes the 2-wide head
        if (wg == 0) {
            float z0 = b20, z1 = b21;
#pragma unroll
            for (int w = 0; w < TPS / 32; w++) {
                float2 v = sPart[p][s][w];
                z0 += v.x; z1 += v.y;
            }
            float o0 = ftanh(z0), o1 = ftanh(z1);
            float nrm = fmaxf(sqrtf(o0 * o0 + o1 * o1), 1e-12f);
            float sel = (xd > 0.f ? o0 : o1) / nrm;
            wav *= sel;
        }
    }

    if (wg == 0) gout[n] = wav;
}

extern "C" void kernel_launch(void* const* d_in, const int* in_sizes, int n_in,
                              void* d_out, int out_size) {
    const float* x  = (const float*)d_in[0];
    const float* W1 = (const float*)d_in[1];
    const float* b1 = (const float*)d_in[2];
    const float* W2 = (const float*)d_in[3];
    const float* b2 = (const float*)d_in[4];
    qnade_kernel<<<NN / SS, BLOCK>>>(x, W1, b1, W2, b2, (float*)d_out);
}